// round 2
// baseline (speedup 1.0000x reference)
#include <cuda_runtime.h>
#include <cuda_bf16.h>

// Problem constants (fixed shapes)
#define NN      50000
#define CC      32
#define HH      32
#define EE      1600000
#define NH      1600000      // N*H
#define FC      64
#define NCLS    2
#define BN_EPS  1e-5f

// Scratch (device globals; no allocation allowed)
__device__ __align__(16) float g_xbn[NN * CC];
__device__ __align__(16) float g_agg[NN * CC];
__device__ __align__(16) float g_agg0[NN * CC];
__device__ float g_hacc[FC];

// ---------------------------------------------------------------------------
// Kernel 1: BatchNorm (eval) + zero the accumulators
// ---------------------------------------------------------------------------
__global__ void bn_zero_kernel(const float* __restrict__ x,
                               const float* __restrict__ gamma,
                               const float* __restrict__ beta,
                               const float* __restrict__ mean,
                               const float* __restrict__ var) {
    int i = blockIdx.x * blockDim.x + threadIdx.x;
    if (i < NN * CC) {
        int c = i & (CC - 1);
        float xv = x[i];
        float s = rsqrtf(var[c] + BN_EPS) * gamma[c];
        g_xbn[i] = (xv - mean[c]) * s + beta[c];
        g_agg[i] = 0.0f;
        g_agg0[i] = 0.0f;
    }
    if (i < FC) g_hacc[i] = 0.0f;
}

// ---------------------------------------------------------------------------
// Kernel 2: edge scatter with vector global reductions
// ---------------------------------------------------------------------------
__device__ __forceinline__ void red_add_v4(float* p, float a, float b, float c, float d) {
    asm volatile("red.global.add.v4.f32 [%0], {%1, %2, %3, %4};"
                 :: "l"(p), "f"(a), "f"(b), "f"(c), "f"(d) : "memory");
}

__global__ void scatter_kernel(const int* __restrict__ edge_index,
                               const float* __restrict__ edge_weight) {
    int e = blockIdx.x * blockDim.x + threadIdx.x;
    if (e >= EE) return;
    int s = edge_index[e];
    int d = edge_index[EE + e];
    float w = edge_weight[e];

    const float4* xr = reinterpret_cast<const float4*>(g_xbn + (size_t)s * CC);
    float* ar = g_agg + (size_t)d * CC;

    float4 v[8];
#pragma unroll
    for (int k = 0; k < 8; k++) v[k] = xr[k];
#pragma unroll
    for (int k = 0; k < 8; k++)
        red_add_v4(ar + 4 * k, w * v[k].x, w * v[k].y, w * v[k].z, w * v[k].w);

    if (s == d) {   // self-loop: T_0 identity term with weight 1.0
        float* a0 = g_agg0 + (size_t)d * CC;
#pragma unroll
        for (int k = 0; k < 8; k++)
            red_add_v4(a0 + 4 * k, v[k].x, v[k].y, v[k].z, v[k].w);
    }
}

// ---------------------------------------------------------------------------
// Kernel 3: fused per-node 32x32 GEMM + ReLU + fc1 (64 x 1.6M) partial dots
// One warp per node; lane = h. fc1_w reads are the only big DRAM stream.
// ---------------------------------------------------------------------------
__global__ __launch_bounds__(256)
void node_fc1_kernel(const float* __restrict__ W,      // [3,32,32]
                     const float* __restrict__ fc1_w)  // [64, 1600000]
{
    __shared__ float sW0[CC * HH];
    __shared__ float sWs[CC * HH];
    for (int i = threadIdx.x; i < CC * HH; i += blockDim.x) {
        sW0[i] = W[i];
        sWs[i] = W[CC * HH + i] + W[2 * CC * HH + i];
    }
    __shared__ float sAcc[FC];
    for (int i = threadIdx.x; i < FC; i += blockDim.x) sAcc[i] = 0.0f;
    __syncthreads();

    float acc[FC];
#pragma unroll
    for (int f = 0; f < FC; f++) acc[f] = 0.0f;

    const int lane   = threadIdx.x & 31;
    const int warp   = (blockIdx.x * blockDim.x + threadIdx.x) >> 5;
    const int nwarps = (gridDim.x * blockDim.x) >> 5;

    for (int n = warp; n < NN; n += nwarps) {
        float av = g_agg[n * CC + lane];
        float a0 = g_agg0[n * CC + lane];

        float r = 0.0f;
#pragma unroll
        for (int c = 0; c < CC; c++)
            r = fmaf(__shfl_sync(0xffffffffu, av, c), sWs[c * HH + lane], r);

        if (__ballot_sync(0xffffffffu, a0 != 0.0f)) {
#pragma unroll
            for (int c = 0; c < CC; c++)
                r = fmaf(__shfl_sync(0xffffffffu, a0, c), sW0[c * HH + lane], r);
        }
        r = fmaxf(r, 0.0f);

        const float* fw = fc1_w + (size_t)n * HH + lane;
#pragma unroll
        for (int f = 0; f < FC; f++)
            acc[f] = fmaf(r, __ldg(fw + (size_t)f * NH), acc[f]);
    }

    // warp-reduce each of the 64 accumulators, then block-, then global-reduce
#pragma unroll
    for (int f = 0; f < FC; f++) {
        float v = acc[f];
        v += __shfl_xor_sync(0xffffffffu, v, 16);
        v += __shfl_xor_sync(0xffffffffu, v, 8);
        v += __shfl_xor_sync(0xffffffffu, v, 4);
        v += __shfl_xor_sync(0xffffffffu, v, 2);
        v += __shfl_xor_sync(0xffffffffu, v, 1);
        if (lane == 0) atomicAdd(&sAcc[f], v);
    }
    __syncthreads();
    for (int i = threadIdx.x; i < FC; i += blockDim.x)
        atomicAdd(&g_hacc[i], sAcc[i]);
}

// ---------------------------------------------------------------------------
// Kernel 4: head — relu(h + fc1_b), then 2x64 GEMV with fc2
// ---------------------------------------------------------------------------
__global__ void head_kernel(const float* __restrict__ fc1_b,
                            const float* __restrict__ fc2_w,
                            const float* __restrict__ fc2_b,
                            float* __restrict__ out) {
    __shared__ float hv[FC];
    int t = threadIdx.x;
    if (t < FC) hv[t] = fmaxf(g_hacc[t] + fc1_b[t], 0.0f);
    __syncthreads();
    if (t < NCLS) {
        float s = fc2_b[t];
#pragma unroll
        for (int f = 0; f < FC; f++) s = fmaf(hv[f], fc2_w[t * FC + f], s);
        out[t] = s;
    }
}

// ---------------------------------------------------------------------------
// launch
// ---------------------------------------------------------------------------
extern "C" void kernel_launch(void* const* d_in, const int* in_sizes, int n_in,
                              void* d_out, int out_size) {
    const float* x        = (const float*)d_in[0];
    const float* ew       = (const float*)d_in[1];
    const float* W        = (const float*)d_in[2];
    const float* bn_gamma = (const float*)d_in[3];
    const float* bn_beta  = (const float*)d_in[4];
    const float* bn_mean  = (const float*)d_in[5];
    const float* bn_var   = (const float*)d_in[6];
    const float* fc1_w    = (const float*)d_in[7];
    const float* fc1_b    = (const float*)d_in[8];
    const float* fc2_w    = (const float*)d_in[9];
    const float* fc2_b    = (const float*)d_in[10];
    const int*   ei       = (const int*)d_in[11];
    float* out            = (float*)d_out;

    bn_zero_kernel<<<(NN * CC + 255) / 256, 256>>>(x, bn_gamma, bn_beta, bn_mean, bn_var);
    scatter_kernel<<<(EE + 255) / 256, 256>>>(ei, ew);
    node_fc1_kernel<<<296, 256>>>(W, fc1_w);
    head_kernel<<<1, 64>>>(fc1_b, fc2_w, fc2_b, out);
}